// round 11
// baseline (speedup 1.0000x reference)
#include <cuda_runtime.h>
#include <math_constants.h>

// AutoCorrelation (Autoformer): q,k,v (32,8,2048,64) fp32.
// corr[r,d] = sum_j q[r,j]*k[r,(j-d)%64]; top-4 over d, softmax, gather v.
// out = [ V (B,H,L,E) | corr^T (B,E,H,L) ]
//
// One thread = one row; q AND k register-resident so the corr loop is a pure
// FFMA stream (no smem/local dependency). launch_bounds(64,4) gives ptxas a
// 256-reg ceiling: live set ~190 fits WITHOUT the spills that poisoned R10
// (regs capped 168 there). 32-bit addressing throughout to shrink misc regs.

#define STRS 68   // floats per tile row = 17 float4: 16B aligned, conflict-free

#define CP_ASYNC4(smem_u32, gptr) \
    asm volatile("cp.async.ca.shared.global [%0], [%1], 4;" \
                 :: "r"(smem_u32), "l"(gptr) : "memory")
#define CP_COMMIT()  asm volatile("cp.async.commit_group;" ::: "memory")
#define CP_WAIT(N)   asm volatile("cp.async.wait_group %0;" :: "n"(N) : "memory")

// topk insert, strict > keeps lowest index on ties (lax.top_k order)
#define TOPK_INS(vv, d)                                                          \
    if (vv > w3) {                                                               \
        if (vv > w2) {                                                           \
            if (vv > w1) {                                                       \
                if (vv > w0) { w3=w2;i3=i2; w2=w1;i2=i1; w1=w0;i1=i0; w0=vv;i0=d;}\
                else          { w3=w2;i3=i2; w2=w1;i2=i1; w1=vv;i1=d; }          \
            } else            { w3=w2;i3=i2; w2=vv;i2=d; }                       \
        } else                { w3=vv;i3=d; }                                    \
    }

__global__ void __launch_bounds__(64, 4)
autocorr_kernel(const float* __restrict__ gq,
                const float* __restrict__ gk,
                const float* __restrict__ gv,
                float* __restrict__ outV,
                float* __restrict__ outC) {
    __shared__ __align__(16) float tile[2][32][STRS];  // one tile/warp: k -> q -> v

    const int w    = threadIdx.x >> 5;
    const int lane = threadIdx.x & 31;
    float* Tf = &tile[w][0][0];
    const unsigned Ts = (unsigned)__cvta_generic_to_shared(Tf);

    const unsigned r0  = ((unsigned)blockIdx.x * 2u + (unsigned)w) * 32u;  // 32 rows/warp
    const unsigned off = r0 * 64u;            // elements; max 33.5M, fits 32-bit

    // stage 32 rows x 64 floats: coalesced LDG, conflict-free STS
#define STAGE(gsrc)                                                          \
    _Pragma("unroll 8")                                                      \
    for (int it = 0; it < 64; it++) {                                        \
        Tf[(it >> 1) * STRS + ((it & 1) << 5) + lane]                        \
            = gsrc[off + (unsigned)(it * 32) + (unsigned)lane];              \
    }

    // ---- k: stage, pull row into 64 regs (LDS.128) ----
    STAGE(gk);
    __syncwarp();
    float kr[64];
    {
        const float4* P = (const float4*)(Tf + lane * STRS);
        #pragma unroll
        for (int t = 0; t < 16; t++) {
            float4 f = P[t];
            kr[4*t] = f.x; kr[4*t+1] = f.y; kr[4*t+2] = f.z; kr[4*t+3] = f.w;
        }
    }
    __syncwarp();

    // ---- q: stage, pull row into 64 regs ----
    STAGE(gq);
    __syncwarp();
    float qr[64];
    {
        const float4* P = (const float4*)(Tf + lane * STRS);
        #pragma unroll
        for (int t = 0; t < 16; t++) {
            float4 f = P[t];
            qr[4*t] = f.x; qr[4*t+1] = f.y; qr[4*t+2] = f.z; qr[4*t+3] = f.w;
        }
    }
    __syncwarp();

    // ---- v prefetch into the (now dead) tile; hides behind corr ----
    #pragma unroll 8
    for (int it = 0; it < 64; it++) {
        const int fi = (it >> 1) * STRS + ((it & 1) << 5) + lane;
        CP_ASYNC4(Ts + 4u * (unsigned)fi, gv + off + (unsigned)(it * 32 + lane));
    }
    CP_COMMIT();

    // ---- top-4 state ----
    float w0=-CUDART_INF_F, w1=-CUDART_INF_F, w2=-CUDART_INF_F, w3=-CUDART_INF_F;
    int   i0=0, i1=0, i2=0, i3=0;

    // corr^T: rows of this warp share (b,h); l = l0 + lane (32-bit math)
    const unsigned b = r0 >> 14;
    const unsigned h = (r0 >> 11) & 7u;
    const unsigned l = (r0 & 2047u) + (unsigned)lane;
    float* cA = outC + b * (64u * 8u * 2048u) + h * 2048u + l;

    // ---- correlation: 2 passes x 32 accumulators, pure register FFMA ----
    #pragma unroll
    for (int p = 0; p < 2; p++) {
        float c[32];
        #pragma unroll
        for (int dd = 0; dd < 32; dd++) c[dd] = 0.f;

        #pragma unroll
        for (int j = 0; j < 64; j++) {
            const float qj = qr[j];
            #pragma unroll
            for (int dd = 0; dd < 32; dd++)
                c[dd] = fmaf(qj, kr[(j + 64 - p * 32 - dd) & 63], c[dd]);
        }

        // stores: one base, compile-time immediate offsets (d*16384 floats)
        #pragma unroll
        for (int dd = 0; dd < 32; dd++) {
            const int d = p * 32 + dd;
            const float v = c[dd];
            cA[(unsigned)d * 16384u] = v;
            TOPK_INS(v, d);
        }
    }

    // ---- softmax over the 4 weights (w0 is the max) ----
    const float e1 = __expf(w1 - w0), e2 = __expf(w2 - w0), e3 = __expf(w3 - w0);
    const float inv = 1.f / (1.f + e1 + e2 + e3);
    const float t0 = inv, t1 = e1 * inv, t2 = e2 * inv, t3 = e3 * inv;

    // ---- v ready (prefetched behind corr) ----
    CP_WAIT(0);
    __syncwarp();

    // ---- gather + direct float4 V store (L2 merges half-sectors) ----
    {
        const float* vp = Tf + lane * STRS;
        float* outR = outV + off + (unsigned)(lane * 64);
        #pragma unroll
        for (int eg = 0; eg < 16; eg++) {
            float4 o;
            #pragma unroll
            for (int s = 0; s < 4; s++) {
                const int e = eg * 4 + s;
                float sa =      t0 * vp[(e + i0) & 63];
                sa = fmaf(t1, vp[(e + i1) & 63], sa);
                sa = fmaf(t2, vp[(e + i2) & 63], sa);
                sa = fmaf(t3, vp[(e + i3) & 63], sa);
                (&o.x)[s] = sa;
            }
            *(float4*)(outR + eg * 4) = o;
        }
    }
}

extern "C" void kernel_launch(void* const* d_in, const int* in_sizes, int n_in,
                              void* d_out, int out_size) {
    const float* q = (const float*)d_in[0];
    const float* k = (const float*)d_in[1];
    const float* v = (const float*)d_in[2];
    float* outV = (float*)d_out;
    float* outC = (float*)d_out + (long long)32 * 8 * 2048 * 64;

    const int rows    = 32 * 8 * 2048;      // 524288
    const int nblocks = rows / 64;          // 8192 blocks, 2 warps (64 rows) each
    autocorr_kernel<<<nblocks, 64>>>(q, k, v, outV, outC);
}

// round 13
// speedup vs baseline: 1.1724x; 1.1724x over previous
#include <cuda_runtime.h>
#include <math_constants.h>

// AutoCorrelation (Autoformer): q,k,v (32,8,2048,64) fp32.
// corr[r,d] = sum_j q[r,j]*k[r,(j-d)%64]; top-4 over d, softmax, gather v.
// out = [ V (B,H,L,E) | corr^T (B,E,H,L) ]
//
// R2 corr core (thread = row, kr[64] resident, scalar imm-offset q LDS) at
// the untried 146-reg / 14-warp point: c[16] x 4 passes, cp.async staging
// (zero register cost), ONE 32x65 tile per warp reused k -> q -> v, masked
// gather. Goal: +2 warps/SM over R2 without triggering the R7 spill.

#define STRS 65   // odd scalar stride: bank (lane + j) % 32, conflict-free

#define CP_ASYNC4(smem_u32, gptr) \
    asm volatile("cp.async.ca.shared.global [%0], [%1], 4;" \
                 :: "r"(smem_u32), "l"(gptr) : "memory")
#define CP_COMMIT()  asm volatile("cp.async.commit_group;" ::: "memory")
#define CP_WAIT0()   asm volatile("cp.async.wait_group 0;" ::: "memory")

// topk insert, strict > keeps lowest index on ties (lax.top_k order)
#define TOPK_INS(vv, d)                                                          \
    if (vv > w3) {                                                               \
        if (vv > w2) {                                                           \
            if (vv > w1) {                                                       \
                if (vv > w0) { w3=w2;i3=i2; w2=w1;i2=i1; w1=w0;i1=i0; w0=vv;i0=d;}\
                else          { w3=w2;i3=i2; w2=w1;i2=i1; w1=vv;i1=d; }          \
            } else            { w3=w2;i3=i2; w2=vv;i2=d; }                       \
        } else                { w3=vv;i3=d; }                                    \
    }

__global__ void __launch_bounds__(64, 7)
autocorr_kernel(const float* __restrict__ gq,
                const float* __restrict__ gk,
                const float* __restrict__ gv,
                float* __restrict__ outV,
                float* __restrict__ outC) {
    __shared__ float tile[2][32][STRS];     // ONE tile per warp, reused k->q->v

    const int w    = threadIdx.x >> 5;
    const int lane = threadIdx.x & 31;
    float* Tf = &tile[w][0][0];
    const unsigned Ts = (unsigned)__cvta_generic_to_shared(Tf);

    const unsigned r0  = ((unsigned)blockIdx.x * 2u + (unsigned)w) * 32u;
    const unsigned off = r0 * 64u;          // element offset, fits 32-bit

    // async-stage 32 rows x 64 floats (coalesced gmem, conflict-free smem,
    // ZERO register cost - LDGSTS bypasses the RF)
#define ASTAGE(gsrc)                                                         \
    _Pragma("unroll 8")                                                      \
    for (int it = 0; it < 64; it++) {                                        \
        const int fi = (it >> 1) * STRS + ((it & 1) << 5) + lane;            \
        CP_ASYNC4(Ts + 4u * (unsigned)fi,                                    \
                  gsrc + off + (unsigned)(it * 32 + lane));                  \
    }

    // ---- k: async stage, pull row into 64 regs ----
    ASTAGE(gk); CP_COMMIT();
    CP_WAIT0();
    __syncwarp();
    float kr[64];
    #pragma unroll
    for (int j = 0; j < 64; j++) kr[j] = Tf[lane * STRS + j];
    __syncwarp();

    // ---- q: async stage into the same tile ----
    ASTAGE(gq); CP_COMMIT();
    CP_WAIT0();
    __syncwarp();

    // ---- top-4 state ----
    float w0=-CUDART_INF_F, w1=-CUDART_INF_F, w2=-CUDART_INF_F, w3=-CUDART_INF_F;
    int   i0=0, i1=0, i2=0, i3=0;

    // corr^T: rows of this warp share (b,h); l = l0 + lane
    const unsigned b = r0 >> 14;
    const unsigned h = (r0 >> 11) & 7u;
    const unsigned l = (r0 & 2047u) + (unsigned)lane;
    float* cA = outC + b * (64u * 8u * 2048u) + h * 2048u + l;

    // ---- correlation: 4 passes x 16 accumulators (live set ~120 regs) ----
    #pragma unroll
    for (int p = 0; p < 4; p++) {
        float c[16];
        #pragma unroll
        for (int dd = 0; dd < 16; dd++) c[dd] = 0.f;

        #pragma unroll
        for (int j = 0; j < 64; j++) {
            const float qj = Tf[lane * STRS + j];   // 1-phase LDS, reused x16
            #pragma unroll
            for (int dd = 0; dd < 16; dd++)
                c[dd] = fmaf(qj, kr[(j + 64 - p * 16 - dd) & 63], c[dd]);
        }

        #pragma unroll
        for (int dd = 0; dd < 16; dd++) {
            const int d = p * 16 + dd;
            const float v = c[dd];
            cA[(unsigned)d * 16384u] = v;           // lanes contiguous in l
            TOPK_INS(v, d);
        }
    }

    // ---- softmax over the 4 weights (w0 is the max) ----
    const float e1 = __expf(w1 - w0), e2 = __expf(w2 - w0), e3 = __expf(w3 - w0);
    const float inv = 1.f / (1.f + e1 + e2 + e3);
    const float t0 = inv, t1 = e1 * inv, t2 = e2 * inv, t3 = e3 * inv;

    // ---- v: async stage into the same tile (q dead) ----
    __syncwarp();
    ASTAGE(gv); CP_COMMIT();
    CP_WAIT0();
    __syncwarp();

    // ---- masked gather + float4 V store (L2 merges half-sectors) ----
    {
        const float* vp = Tf + lane * STRS;
        float* outR = outV + off + (unsigned)(lane * 64);
        #pragma unroll
        for (int eg = 0; eg < 16; eg++) {
            float4 o;
            #pragma unroll
            for (int s = 0; s < 4; s++) {
                const int e = eg * 4 + s;
                float sa =      t0 * vp[(e + i0) & 63];
                sa = fmaf(t1, vp[(e + i1) & 63], sa);
                sa = fmaf(t2, vp[(e + i2) & 63], sa);
                sa = fmaf(t3, vp[(e + i3) & 63], sa);
                (&o.x)[s] = sa;
            }
            *(float4*)(outR + eg * 4) = o;
        }
    }
}

extern "C" void kernel_launch(void* const* d_in, const int* in_sizes, int n_in,
                              void* d_out, int out_size) {
    const float* q = (const float*)d_in[0];
    const float* k = (const float*)d_in[1];
    const float* v = (const float*)d_in[2];
    float* outV = (float*)d_out;
    float* outC = (float*)d_out + (long long)32 * 8 * 2048 * 64;

    const int rows    = 32 * 8 * 2048;      // 524288
    const int nblocks = rows / 64;          // 8192 blocks, 2 warps (64 rows) each
    autocorr_kernel<<<nblocks, 64>>>(q, k, v, outV, outC);
}

// round 14
// speedup vs baseline: 2.1391x; 1.8245x over previous
#include <cuda_runtime.h>
#include <math_constants.h>

// AutoCorrelation (Autoformer): q,k,v (32,8,2048,64) fp32.
// corr[r,d] = sum_j q[r,j]*k[r,(j-d)%64]; top-4 over d, softmax, gather v.
// out = [ V (B,H,L,E) | corr^T (B,E,H,L) ]
//
// TWO lanes per row (lane parity = d-half of 32). k is NOT register-resident:
// it streams through a 32-deep rotating register window with compile-time
// slot indices (1 LDS refill per j). Core live set = wv[32]+c[32] ~ 64 regs,
// so the kernel honestly fits launch_bounds(128,5)=102 regs -> 20 warps/SM,
// breaking the 168-reg / 12-warp wall that capped R2/R5/R8 at ~244us.

#define STRT 65   // tile row stride (floats); bank (row + col) % 32

#define CP_ASYNC4(smem_u32, gptr) \
    asm volatile("cp.async.ca.shared.global [%0], [%1], 4;" \
                 :: "r"(smem_u32), "l"(gptr) : "memory")
#define CP_COMMIT() asm volatile("cp.async.commit_group;" ::: "memory")
#define CP_WAIT0()  asm volatile("cp.async.wait_group 0;" ::: "memory")

// topk insert, strict > keeps lowest index on ties (lax.top_k order)
#define TOPK_INS(vv, d)                                                          \
    if (vv > w3) {                                                               \
        if (vv > w2) {                                                           \
            if (vv > w1) {                                                       \
                if (vv > w0) { w3=w2;i3=i2; w2=w1;i2=i1; w1=w0;i1=i0; w0=vv;i0=d;}\
                else          { w3=w2;i3=i2; w2=w1;i2=i1; w1=vv;i1=d; }          \
            } else            { w3=w2;i3=i2; w2=vv;i2=d; }                       \
        } else                { w3=vv;i3=d; }                                    \
    }

// one merge round: a = low-d sorted-4 list, b = high-d; a wins ties (lower d)
#define MSTEP(mo, mio) {                                                         \
    const bool ta = (a0 >= b0);                                                  \
    mo = ta ? a0 : b0; mio = ta ? ai0 : bi0;                                     \
    if (ta) { a0=a1; ai0=ai1; a1=a2; ai1=ai2; a2=a3; ai2=ai3; a3=-CUDART_INF_F; }\
    else    { b0=b1; bi0=bi1; b1=b2; bi1=bi2; b2=b3; bi2=bi3; b3=-CUDART_INF_F; }}

__global__ void __launch_bounds__(128, 5)
autocorr_kernel(const float* __restrict__ gq,
                const float* __restrict__ gk,
                const float* __restrict__ gv,
                float* __restrict__ outV,
                float* __restrict__ outC) {
    __shared__ float TQ[4][16][STRT];   // per-warp q tile, reused for v
    __shared__ float TK[4][16][STRT];   // per-warp k tile

    const int w    = threadIdx.x >> 5;
    const int lane = threadIdx.x & 31;
    const int row  = lane >> 1;         // 0..15 (row within warp)
    const int dh   = lane & 1;          // d-half selector
    const int d0   = dh << 5;           // 0 or 32

    float* Q = &TQ[w][0][0];
    float* K = &TK[w][0][0];
    const unsigned Qs = (unsigned)__cvta_generic_to_shared(Q);
    const unsigned Ks = (unsigned)__cvta_generic_to_shared(K);

    const unsigned r0  = ((unsigned)blockIdx.x * 4u + (unsigned)w) * 16u; // 16 rows/warp
    const unsigned off = r0 * 64u;      // element offset, fits 32-bit

    // async-stage 16 rows x 64 floats (coalesced gmem, zero register cost)
#define ASTAGE(base_u32, gsrc)                                               \
    _Pragma("unroll 8")                                                      \
    for (int it = 0; it < 32; it++) {                                        \
        const int f  = it * 32 + lane;                                       \
        const int fi = (f >> 6) * STRT + (f & 63);                           \
        CP_ASYNC4(base_u32 + 4u * (unsigned)fi, gsrc + off + (unsigned)f);   \
    }

    ASTAGE(Ks, gk);
    ASTAGE(Qs, gq);
    CP_COMMIT(); CP_WAIT0();
    __syncwarp();

    const float* Krow = K + row * STRT;
    const float* Qrow = Q + row * STRT;

    // ---- rotating 32-deep k window; (x - d0) & 63 == x ^ d0 for d0 in {0,32}
    float wv[32];
    #pragma unroll
    for (int t = -31; t < 0; t++)
        wv[(t + 32) & 31] = Krow[((t + 64) & 63) ^ d0];

    float c[32];
    #pragma unroll
    for (int i = 0; i < 32; i++) c[i] = 0.f;

    #pragma unroll
    for (int j = 0; j < 64; j++) {
        wv[j & 31] = Krow[j ^ d0];              // refill slot j&31
        const float qj = Qrow[j];
        #pragma unroll
        for (int dd = 0; dd < 32; dd++)         // c[dd] += q[j]*k[(j-d0-dd)&63]
            c[dd] = fmaf(qj, wv[(j - dd) & 31], c[dd]);
    }

    // ---- corr^T store base + local top-4 over this thread's 32 d values ----
    const unsigned bb = r0 >> 14;
    const unsigned hh = (r0 >> 11) & 7u;
    const unsigned ll = (r0 & 2047u) + (unsigned)row;
    float* cA = outC + bb * (64u * 8u * 2048u) + hh * 2048u + ll
                     + (unsigned)d0 * 16384u;

    float w0=-CUDART_INF_F, w1=-CUDART_INF_F, w2=-CUDART_INF_F, w3=-CUDART_INF_F;
    int   i0=0, i1=0, i2=0, i3=0;
    #pragma unroll
    for (int dd = 0; dd < 32; dd++) {
        const float v = c[dd];
        const int   d = d0 + dd;
        cA[(unsigned)dd * 16384u] = v;          // 16 contiguous l per half: full sectors
        TOPK_INS(v, d);
    }

    // ---- merge top-4 with partner lane (other d-half) ----
    const float pw0=__shfl_xor_sync(0xFFFFFFFFu,w0,1), pw1=__shfl_xor_sync(0xFFFFFFFFu,w1,1),
                pw2=__shfl_xor_sync(0xFFFFFFFFu,w2,1), pw3=__shfl_xor_sync(0xFFFFFFFFu,w3,1);
    const int   pi0=__shfl_xor_sync(0xFFFFFFFFu,i0,1), pi1=__shfl_xor_sync(0xFFFFFFFFu,i1,1),
                pi2=__shfl_xor_sync(0xFFFFFFFFu,i2,1), pi3=__shfl_xor_sync(0xFFFFFFFFu,i3,1);
    float a0 = dh ? pw0 : w0, a1 = dh ? pw1 : w1, a2 = dh ? pw2 : w2, a3 = dh ? pw3 : w3;
    int  ai0 = dh ? pi0 : i0, ai1 = dh ? pi1 : i1, ai2 = dh ? pi2 : i2, ai3 = dh ? pi3 : i3;
    float b0 = dh ? w0 : pw0, b1 = dh ? w1 : pw1, b2 = dh ? w2 : pw2, b3 = dh ? w3 : pw3;
    int  bi0 = dh ? i0 : pi0, bi1 = dh ? i1 : pi1, bi2 = dh ? i2 : pi2, bi3 = dh ? i3 : pi3;

    float m0, m1, m2, m3; int mi0, mi1, mi2, mi3;
    MSTEP(m0, mi0) MSTEP(m1, mi1) MSTEP(m2, mi2) MSTEP(m3, mi3)

    // ---- softmax over the 4 weights (m0 is the max) ----
    const float e1 = __expf(m1 - m0), e2 = __expf(m2 - m0), e3 = __expf(m3 - m0);
    const float inv = 1.f / (1.f + e1 + e2 + e3);
    const float t0 = inv, t1 = e1 * inv, t2 = e2 * inv, t3 = e3 * inv;

    // ---- v into the q tile (q dead) ----
    __syncwarp();
    ASTAGE(Qs, gv);
    CP_COMMIT(); CP_WAIT0();
    __syncwarp();

    // ---- gather: this thread covers e in [d0, d0+32) of its row ----
    {
        const float* Vrow = Q + row * STRT;
        const int g0 = d0 + mi0, g1 = d0 + mi1, g2 = d0 + mi2, g3 = d0 + mi3;
        float* outR = outV + off + (unsigned)(row * 64 + d0);
        #pragma unroll
        for (int eg = 0; eg < 8; eg++) {
            float4 o;
            #pragma unroll
            for (int s = 0; s < 4; s++) {
                const int e = eg * 4 + s;       // global e = d0 + e (folded into g*)
                float sa =      t0 * Vrow[(g0 + e) & 63];
                sa = fmaf(t1, Vrow[(g1 + e) & 63], sa);
                sa = fmaf(t2, Vrow[(g2 + e) & 63], sa);
                sa = fmaf(t3, Vrow[(g3 + e) & 63], sa);
                (&o.x)[s] = sa;
            }
            *(float4*)(outR + eg * 4) = o;      // 32 lanes -> 4KB contiguous
        }
    }
}

extern "C" void kernel_launch(void* const* d_in, const int* in_sizes, int n_in,
                              void* d_out, int out_size) {
    const float* q = (const float*)d_in[0];
    const float* k = (const float*)d_in[1];
    const float* v = (const float*)d_in[2];
    float* outV = (float*)d_out;
    float* outC = (float*)d_out + (long long)32 * 8 * 2048 * 64;

    const int rows    = 32 * 8 * 2048;      // 524288
    const int nblocks = rows / 64;          // 8192 blocks: 128 thr = 4 warps x 16 rows
    autocorr_kernel<<<nblocks, 128>>>(q, k, v, outV, outC);
}